// round 12
// baseline (speedup 1.0000x reference)
#include <cuda_runtime.h>
#include <cuda_bf16.h>
#include <math.h>

#define BB   8
#define DM   512
#define NH   8
#define DH   64
#define DFF  2048
#define LMAX 1021
#define NMAX 35

// ---------------- scratch (static device globals; no allocation) -------------
__device__ float g_x  [BB*LMAX*DM];
__device__ float g_q  [BB*LMAX*DM];
__device__ float g_k  [BB*LMAX*DM];
__device__ float g_v  [BB*LMAX*DM];
__device__ float g_ctx[BB*LMAX*DM];
__device__ float g_ffh[BB*LMAX*DFF];
__device__ float g_m  [BB*NH*LMAX];
__device__ float g_vmean[BB*NH*DH];
__device__ int   g_top[BB*NH*NMAX];
__device__ int   g_idx[LMAX*NMAX];
__device__ unsigned g_hi[LMAX*NMAX];
__device__ unsigned g_lo[LMAX*NMAX];
__device__ float g_cw [3*DM*DM];

// ---------------- threefry2x32 (20 rounds), host+device ----------------------
__host__ __device__ static inline unsigned rotl32(unsigned v, int d) {
    return (v << d) | (v >> (32 - d));
}
__host__ __device__ static inline void tf2x32(unsigned k0, unsigned k1,
                                              unsigned x0, unsigned x1,
                                              unsigned& o0, unsigned& o1) {
    unsigned ks2 = k0 ^ k1 ^ 0x1BD11BDAu;
    x0 += k0; x1 += k1;
#define TFR(r) { x0 += x1; x1 = rotl32(x1, r); x1 ^= x0; }
    TFR(13) TFR(15) TFR(26) TFR(6)   x0 += k1;  x1 += ks2 + 1u;
    TFR(17) TFR(29) TFR(16) TFR(24)  x0 += ks2; x1 += k0  + 2u;
    TFR(13) TFR(15) TFR(26) TFR(6)   x0 += k0;  x1 += k1  + 3u;
    TFR(17) TFR(29) TFR(16) TFR(24)  x0 += k1;  x1 += ks2 + 4u;
    TFR(13) TFR(15) TFR(26) TFR(6)   x0 += ks2; x1 += k0  + 5u;
#undef TFR
    o0 = x0; o1 = x1;
}

// ---------------- random bits + randint --------------------------------------
__global__ void k_bits(unsigned k1a, unsigned k1b, unsigned k2a, unsigned k2b, int total) {
    int e = blockIdx.x * 256 + threadIdx.x;
    if (e >= total) return;
    unsigned o0, o1;
    tf2x32(k1a, k1b, 0u, (unsigned)e, o0, o1);
    g_hi[e] = o0 ^ o1;
    tf2x32(k2a, k2b, 0u, (unsigned)e, o0, o1);
    g_lo[e] = o0 ^ o1;
}

__global__ void k_randint(int total, unsigned span) {
    int e = blockIdx.x * 256 + threadIdx.x;
    if (e >= total) return;
    unsigned mult = 65536u % span;
    mult = (mult * mult) % span;
    unsigned off = (g_hi[e] % span) * mult + (g_lo[e] % span);
    g_idx[e] = (int)(off % span);
}

// ---------------- token embedding + positional encoding ----------------------
__global__ void k_embed(const float* __restrict__ xe, const float* __restrict__ tw,
                        float* __restrict__ x, int L) {
    int i = blockIdx.x * 256 + threadIdx.x;
    if (i >= BB * L * DM) return;
    int dm  = i % DM;
    int rem = i / DM;
    int l   = rem % L;
    int b   = rem / L;
    int lm1 = (l == 0) ? L - 1 : l - 1;
    int lp1 = (l == L - 1) ? 0 : l + 1;
    const float* x0 = xe + (size_t)(b * L + lm1) * 12;
    const float* x1 = xe + (size_t)(b * L + l)   * 12;
    const float* x2 = xe + (size_t)(b * L + lp1) * 12;
    const float* wp = tw + (size_t)dm * 36;
    float acc = 0.f;
#pragma unroll
    for (int c = 0; c < 12; c++)
        acc += x0[c] * wp[c * 3] + x1[c] * wp[c * 3 + 1] + x2[c] * wp[c * 3 + 2];
    float freq = expf((float)((dm >> 1) * 2) * (-1.7988946039015980e-2f)); // -ln(1e4)/512
    float a = (float)l * freq;
    acc += (dm & 1) ? cosf(a) : sinf(a);
    x[i] = acc;
}

// ---------------- 3xBF16 tensor-core GEMM: C = act(A*W^T [+C] [+bias]) -------
// A: M x K (optional per-batch circular row shift), W: N x K row-major.
// Operands split hi/lo in bf16 at smem-store time; 3 MMAs (m16n8k16) per pair:
// hi*hi + hi*lo + lo*hi, fp32 accumulate. Effective precision ~2^-16 per input.

__device__ __forceinline__ void mma_bf16(float* c, const unsigned* a, const unsigned* b) {
    asm volatile(
        "mma.sync.aligned.m16n8k16.row.col.f32.bf16.bf16.f32 "
        "{%0,%1,%2,%3}, {%4,%5,%6,%7}, {%8,%9}, {%0,%1,%2,%3};"
        : "+f"(c[0]), "+f"(c[1]), "+f"(c[2]), "+f"(c[3])
        : "r"(a[0]), "r"(a[1]), "r"(a[2]), "r"(a[3]), "r"(b[0]), "r"(b[1]));
}

// split a pair of floats into packed bf16x2 hi and lo words
__device__ __forceinline__ void split2(float x0, float x1, unsigned& hi, unsigned& lo) {
    __nv_bfloat162 h = __floats2bfloat162_rn(x0, x1);
    float h0 = __bfloat162float(h.x), h1 = __bfloat162float(h.y);
    __nv_bfloat162 l = __floats2bfloat162_rn(x0 - h0, x1 - h1);
    hi = *(unsigned*)&h;
    lo = *(unsigned*)&l;
}

#define KW 20  // 16 k-words (32 bf16) + pad 4 -> conflict-free fragment loads

__global__ void __launch_bounds__(256, 2)
k_gemm(const float* __restrict__ A, const float* __restrict__ W,
       const float* __restrict__ bias, float* __restrict__ C,
       int M, int N, int K, int act, int accum, int circL, int shift) {
    __shared__ unsigned AsH[128][KW], AsL[128][KW];
    __shared__ unsigned BsH[128][KW], BsL[128][KW];

    int bm = blockIdx.y * 128, bn = blockIdx.x * 128;
    int tid  = threadIdx.x;
    int warp = tid >> 5, lane = tid & 31;
    int wm = warp >> 2;          // 0..1 -> m offset wm*64
    int wn = warp & 3;           // 0..3 -> n offset wn*32
    int g  = lane >> 2;          // 0..7
    int cq = lane & 3;           // 0..3

    // load assignment: 2 threads per row, 16 floats (8 words) each
    int lrow = tid >> 1;
    int kqf  = (tid & 1) * 16;   // float offset within 32-wide k tile
    int kqw  = (tid & 1) * 8;    // word offset

    // A row mapping (circular shift for conv variant)
    int grow = bm + lrow;
    long arow = -1;
    if (grow < M) {
        if (circL > 0) {
            int b_ = grow / circL;
            int l_ = grow - b_ * circL + shift;
            if (l_ < 0) l_ += circL;
            if (l_ >= circL) l_ -= circL;
            arow = (long)b_ * circL + l_;
        } else arow = grow;
    }
    int wrow = bn + lrow; // N multiple of 128

    float acc[4][4][4];
#pragma unroll
    for (int i = 0; i < 4; i++)
#pragma unroll
        for (int j = 0; j < 4; j++)
#pragma unroll
            for (int e = 0; e < 4; e++) acc[i][j][e] = 0.f;

    for (int kt = 0; kt < K; kt += 32) {
#pragma unroll
        for (int i = 0; i < 4; i++) {
            float4 av = make_float4(0.f, 0.f, 0.f, 0.f);
            if (arow >= 0) av = *(const float4*)(A + (size_t)arow * K + kt + kqf + i * 4);
            unsigned h0, l0, h1, l1;
            split2(av.x, av.y, h0, l0);
            split2(av.z, av.w, h1, l1);
            AsH[lrow][kqw + 2 * i]     = h0;
            AsH[lrow][kqw + 2 * i + 1] = h1;
            AsL[lrow][kqw + 2 * i]     = l0;
            AsL[lrow][kqw + 2 * i + 1] = l1;

            float4 wv = *(const float4*)(W + (size_t)wrow * K + kt + kqf + i * 4);
            split2(wv.x, wv.y, h0, l0);
            split2(wv.z, wv.w, h1, l1);
            BsH[lrow][kqw + 2 * i]     = h0;
            BsH[lrow][kqw + 2 * i + 1] = h1;
            BsL[lrow][kqw + 2 * i]     = l0;
            BsL[lrow][kqw + 2 * i + 1] = l1;
        }
        __syncthreads();

#pragma unroll
        for (int ks = 0; ks < 2; ks++) {
            int kb = ks * 8;
            unsigned bh[4][2], bl[4][2];
#pragma unroll
            for (int j = 0; j < 4; j++) {
                int n0 = wn * 32 + j * 8 + g;
                bh[j][0] = BsH[n0][kb + cq];
                bh[j][1] = BsH[n0][kb + cq + 4];
                bl[j][0] = BsL[n0][kb + cq];
                bl[j][1] = BsL[n0][kb + cq + 4];
            }
#pragma unroll
            for (int i = 0; i < 4; i++) {
                int m0 = wm * 64 + i * 16;
                unsigned ah[4], al[4];
                ah[0] = AsH[m0 + g    ][kb + cq];
                ah[1] = AsH[m0 + g + 8][kb + cq];
                ah[2] = AsH[m0 + g    ][kb + cq + 4];
                ah[3] = AsH[m0 + g + 8][kb + cq + 4];
                al[0] = AsL[m0 + g    ][kb + cq];
                al[1] = AsL[m0 + g + 8][kb + cq];
                al[2] = AsL[m0 + g    ][kb + cq + 4];
                al[3] = AsL[m0 + g + 8][kb + cq + 4];
#pragma unroll
                for (int j = 0; j < 4; j++) {
                    mma_bf16(acc[i][j], ah, bl[j]);   // hi * lo
                    mma_bf16(acc[i][j], al, bh[j]);   // lo * hi
                    mma_bf16(acc[i][j], ah, bh[j]);   // hi * hi
                }
            }
        }
        __syncthreads();
    }

    // epilogue
#pragma unroll
    for (int i = 0; i < 4; i++) {
        int r0 = bm + wm * 64 + i * 16 + g;
        int r1 = r0 + 8;
#pragma unroll
        for (int j = 0; j < 4; j++) {
            int col = bn + wn * 32 + j * 8 + 2 * cq;
#pragma unroll
            for (int hrow = 0; hrow < 2; hrow++) {
                int r = hrow ? r1 : r0;
                if (r >= M) continue;
                float v0 = acc[i][j][hrow * 2 + 0];
                float v1 = acc[i][j][hrow * 2 + 1];
                size_t base = (size_t)r * N + col;
                if (accum) { v0 += C[base]; v1 += C[base + 1]; }
                if (bias)  { v0 += bias[col]; v1 += bias[col + 1]; }
                if (act == 1) {
                    v0 = 0.5f * v0 * (1.f + erff(v0 * 0.70710678118654752f));
                    v1 = 0.5f * v1 * (1.f + erff(v1 * 0.70710678118654752f));
                }
                C[base] = v0; C[base + 1] = v1;
            }
        }
    }
}

// ---------------- residual + layernorm (in place on x) -----------------------
__global__ void k_ln(float* __restrict__ x, const float* __restrict__ r,
                     const float* __restrict__ w, const float* __restrict__ b, int Mrows) {
    int row = blockIdx.x;
    if (row >= Mrows) return;
    int tid = threadIdx.x; // 128 threads, 4 elems each
    float4 v = *(float4*)(x + (size_t)row * DM + tid * 4);
    if (r) {
        float4 rv = *(const float4*)(r + (size_t)row * DM + tid * 4);
        v.x += rv.x; v.y += rv.y; v.z += rv.z; v.w += rv.w;
    }
    __shared__ float a1[128], a2[128];
    a1[tid] = v.x + v.y + v.z + v.w;
    a2[tid] = v.x * v.x + v.y * v.y + v.z * v.z + v.w * v.w;
    __syncthreads();
    for (int s = 64; s > 0; s >>= 1) {
        if (tid < s) { a1[tid] += a1[tid + s]; a2[tid] += a2[tid + s]; }
        __syncthreads();
    }
    float mean = a1[0] * (1.f / 512.f);
    float var  = a2[0] * (1.f / 512.f) - mean * mean;
    float rs   = rsqrtf(var + 1e-5f);
    int c = tid * 4;
    float4 o;
    o.x = (v.x - mean) * rs * w[c + 0] + b[c + 0];
    o.y = (v.y - mean) * rs * w[c + 1] + b[c + 1];
    o.z = (v.z - mean) * rs * w[c + 2] + b[c + 2];
    o.w = (v.w - mean) * rs * w[c + 3] + b[c + 3];
    *(float4*)(x + (size_t)row * DM + tid * 4) = o;
}

// ---------------- sparsity measure m[b,h,l] -----------------------------------
__global__ void k_measure(const float* __restrict__ q, const float* __restrict__ k,
                          float* __restrict__ m, int L, int n) {
    int w = (blockIdx.x * blockDim.x + threadIdx.x) >> 5;
    int lane = threadIdx.x & 31;
    if (w >= BB * NH * L) return;
    int l  = w % L;
    int bh = w / L;
    int h  = bh % NH;
    int b  = bh / NH;
    const float* qp = q + ((size_t)(b * L + l) * DM + h * DH);
    float q0 = qp[lane], q1 = qp[lane + 32];
    float mx = -INFINITY, sm = 0.f;
    const int* idx = g_idx + l * n;
    for (int s = 0; s < n; s++) {
        int j = idx[s];
        const float* kp = k + ((size_t)(b * L + j) * DM + h * DH);
        float d = q0 * kp[lane] + q1 * kp[lane + 32];
#pragma unroll
        for (int o = 16; o > 0; o >>= 1) d += __shfl_xor_sync(0xffffffffu, d, o);
        mx = fmaxf(mx, d);
        sm += d;
    }
    if (lane == 0) m[(size_t)bh * L + l] = mx - sm / (float)L;
}

// ---------------- per-(b,h) iterative top-k -----------------------------------
__global__ void k_topk(const float* __restrict__ m, int* __restrict__ top, int L, int n) {
    __shared__ float sm[1024];
    __shared__ float rv[256];
    __shared__ int   ri[256];
    int bh = blockIdx.x;
    int tid = threadIdx.x;
    for (int i = tid; i < 1024; i += 256) sm[i] = (i < L) ? m[(size_t)bh * L + i] : -INFINITY;
    __syncthreads();
    for (int it = 0; it < n; it++) {
        float bv = -INFINITY; int bi = 0x7fffffff;
        for (int i = tid; i < L; i += 256) {
            float v = sm[i];
            if (v > bv) { bv = v; bi = i; }
        }
        rv[tid] = bv; ri[tid] = bi;
        __syncthreads();
        for (int s = 128; s > 0; s >>= 1) {
            if (tid < s) {
                float v2 = rv[tid + s]; int i2 = ri[tid + s];
                if (v2 > rv[tid] || (v2 == rv[tid] && i2 < ri[tid])) { rv[tid] = v2; ri[tid] = i2; }
            }
            __syncthreads();
        }
        if (tid == 0) { top[bh * n + it] = ri[0]; sm[ri[0]] = -INFINITY; }
        __syncthreads();
    }
}

// ---------------- mean(v) and context fill ------------------------------------
__global__ void k_vmean(const float* __restrict__ v, float* __restrict__ vm, int L) {
    __shared__ float red[256];
    int bh = blockIdx.x;
    int tid = threadIdx.x;      // 256 threads: d = tid%64, part = tid/64
    int d = tid & 63, part = tid >> 6;
    int h = bh % NH, b = bh / NH;
    float acc = 0.f;
    for (int l = part; l < L; l += 4)
        acc += v[(size_t)(b * L + l) * DM + h * DH + d];
    red[tid] = acc;
    __syncthreads();
    if (tid < 128) red[tid] += red[tid + 128];
    __syncthreads();
    if (tid < 64) vm[bh * DH + d] = (red[tid] + red[tid + 64]) / (float)L;
}
__global__ void k_fill(const float* __restrict__ vm, float* __restrict__ ctx, int L) {
    int i = blockIdx.x * 256 + threadIdx.x;
    if (i >= BB * L * DM) return;
    int c  = i % DM;
    int bl = i / DM;
    int b  = bl / L;
    ctx[i] = vm[(b * NH + (c >> 6)) * DH + (c & 63)];
}

// ---------------- full attention for the n selected queries -------------------
__global__ void k_attn(const float* __restrict__ q, const float* __restrict__ k,
                       const float* __restrict__ v, const int* __restrict__ top,
                       float* __restrict__ ctx, int L, int n) {
    __shared__ float sc[1024];
    __shared__ float qs[64];
    __shared__ float red[256];
    int u  = blockIdx.x % n;
    int bh = blockIdx.x / n;
    int h = bh % NH, b = bh / NH;
    int tid = threadIdx.x;
    int lq = top[bh * n + u];
    if (tid < 64) qs[tid] = q[(size_t)(b * L + lq) * DM + h * DH + tid];
    __syncthreads();
    int warp = tid >> 5, lane = tid & 31;
    for (int lk = warp; lk < L; lk += 8) {
        const float* kp = k + ((size_t)(b * L + lk) * DM + h * DH);
        float d = qs[lane] * kp[lane] + qs[lane + 32] * kp[lane + 32];
#pragma unroll
        for (int o = 16; o > 0; o >>= 1) d += __shfl_xor_sync(0xffffffffu, d, o);
        if (lane == 0) sc[lk] = d * 0.125f;
    }
    __syncthreads();
    float mx = -INFINITY;
    for (int i = tid; i < L; i += 256) mx = fmaxf(mx, sc[i]);
    red[tid] = mx;
    __syncthreads();
    for (int s = 128; s > 0; s >>= 1) {
        if (tid < s) red[tid] = fmaxf(red[tid], red[tid + s]);
        __syncthreads();
    }
    mx = red[0];
    __syncthreads();
    float sum = 0.f;
    for (int i = tid; i < L; i += 256) {
        float e = expf(sc[i] - mx);
        sc[i] = e;
        sum += e;
    }
    red[tid] = sum;
    __syncthreads();
    for (int s = 128; s > 0; s >>= 1) {
        if (tid < s) red[tid] += red[tid + s];
        __syncthreads();
    }
    float inv = 1.f / red[0];
    __syncthreads();
    int d = tid & 63, part = tid >> 6;
    float acc = 0.f;
    for (int lk = part; lk < L; lk += 4)
        acc += sc[lk] * v[(size_t)(b * L + lk) * DM + h * DH + d];
    red[tid] = acc;
    __syncthreads();
    if (tid < 64) {
        float s2 = red[tid] + red[tid + 64] + red[tid + 128] + red[tid + 192];
        ctx[(size_t)(b * L + lq) * DM + h * DH + tid] = s2 * inv;
    }
}

// ---------------- conv weight repack (tap-major) -------------------------------
__global__ void k_convw(const float* __restrict__ cw) {
    int i = blockIdx.x * 256 + threadIdx.x;
    if (i >= 3 * DM * DM) return;
    int t = i / (DM * DM);
    int rem = i % (DM * DM);
    g_cw[i] = cw[(size_t)rem * 3 + t];
}

// ---------------- BN + ELU + maxpool(3, stride 2, pad 1) -----------------------
__global__ void k_pool(const float* __restrict__ hin, float* __restrict__ xout,
                       const float* __restrict__ bnw, const float* __restrict__ bnb,
                       int L, int L2) {
    int i = blockIdx.x * 256 + threadIdx.x;
    if (i >= BB * L2 * DM) return;
    int c = i % DM;
    int rem = i / DM;
    int l2 = rem % L2;
    int b  = rem / L2;
    float s  = bnw[c] * 0.99999500003749977f; // 1/sqrt(1+1e-5)
    float sh = bnb[c];
    float best = -INFINITY;
#pragma unroll
    for (int dj = -1; dj <= 1; dj++) {
        int j = 2 * l2 + dj;
        if (j < 0 || j >= L) continue;
        float vv = hin[(size_t)(b * L + j) * DM + c] * s + sh;
        vv = (vv > 0.f) ? vv : expm1f(vv);
        best = fmaxf(best, vv);
    }
    xout[(size_t)(b * L2 + l2) * DM + c] = best;
}

// ---------------- final: gelu(x) flattened @ proj^T + bias ---------------------
__global__ void k_proj(const float* __restrict__ x, const float* __restrict__ pw,
                       const float* __restrict__ pb, float* __restrict__ out) {
    int cls = blockIdx.x % 10, b = blockIdx.x / 10;
    int tid = threadIdx.x;
    const float* xp = x  + (size_t)b   * 131072;
    const float* wp = pw + (size_t)cls * 131072;
    float acc = 0.f;
    for (int i = tid; i < 131072; i += 256) {
        float xv = xp[i];
        float g = 0.5f * xv * (1.f + erff(xv * 0.70710678118654752f));
        acc += g * wp[i];
    }
    __shared__ float red[256];
    red[tid] = acc;
    __syncthreads();
    for (int s = 128; s > 0; s >>= 1) {
        if (tid < s) red[tid] += red[tid + s];
        __syncthreads();
    }
    if (tid == 0) out[b * 10 + cls] = red[0] + pb[cls];
}

// ---------------- host orchestration -------------------------------------------
static void run_gemm(const float* A, const float* W, const float* bias, float* C,
                     int M, int N, int K, int act, int accum, int circL, int shift) {
    dim3 grid(N / 128, (M + 127) / 128);
    k_gemm<<<grid, 256>>>(A, W, bias, C, M, N, K, act, accum, circL, shift);
}

extern "C" void kernel_launch(void* const* d_in, const int* in_sizes, int n_in,
                              void* d_out, int out_size) {
    const float* x_enc = (const float*)d_in[0];
    const float* tok_w = (const float*)d_in[1];
    const float* wq  = (const float*)d_in[2];
    const float* bq  = (const float*)d_in[3];
    const float* wk  = (const float*)d_in[4];
    const float* bk  = (const float*)d_in[5];
    const float* wv  = (const float*)d_in[6];
    const float* bv  = (const float*)d_in[7];
    const float* wo  = (const float*)d_in[8];
    const float* bo  = (const float*)d_in[9];
    const float* ln1w = (const float*)d_in[10];
    const float* ln1b = (const float*)d_in[11];
    const float* ln2w = (const float*)d_in[12];
    const float* ln2b = (const float*)d_in[13];
    const float* ff1w = (const float*)d_in[14];
    const float* ff1b = (const float*)d_in[15];
    const float* ff2w = (const float*)d_in[16];
    const float* ff2b = (const float*)d_in[17];
    const float* cvw = (const float*)d_in[18];
    const float* cvb = (const float*)d_in[19];
    const float* bnw = (const float*)d_in[20];
    const float* bnb = (const float*)d_in[21];
    const float* nw  = (const float*)d_in[22];
    const float* nb  = (const float*)d_in[23];
    const float* pw  = (const float*)d_in[24];
    const float* pb  = (const float*)d_in[25];
    float* out = (float*)d_out;

    float *xb, *qb, *kb, *vb, *cxb, *fb, *mb, *vmb, *cwb;
    int *tpb;
    cudaGetSymbolAddress((void**)&xb,  g_x);
    cudaGetSymbolAddress((void**)&qb,  g_q);
    cudaGetSymbolAddress((void**)&kb,  g_k);
    cudaGetSymbolAddress((void**)&vb,  g_v);
    cudaGetSymbolAddress((void**)&cxb, g_ctx);
    cudaGetSymbolAddress((void**)&fb,  g_ffh);
    cudaGetSymbolAddress((void**)&mb,  g_m);
    cudaGetSymbolAddress((void**)&vmb, g_vmean);
    cudaGetSymbolAddress((void**)&tpb, g_top);
    cudaGetSymbolAddress((void**)&cwb, g_cw);

    // ---- per-layer threefry keys (jax.random.split(key(42), 3), partitionable) ----
    unsigned k1a[3], k1b[3], k2a[3], k2b[3];
    for (int l = 0; l < 3; l++) {
        unsigned ka, kb2;
        tf2x32(0u, 42u, 0u, (unsigned)l, ka, kb2);       // layer key
        tf2x32(ka, kb2, 0u, 0u, k1a[l], k1b[l]);         // randint higher key
        tf2x32(ka, kb2, 0u, 1u, k2a[l], k2b[l]);         // randint lower key
    }

    int L = LMAX;
    k_embed<<<(BB * L * DM + 255) / 256, 256>>>(x_enc, tok_w, xb, L);

    for (int l = 0; l < 3; l++) {
        int M = BB * L;
        int n = 5 * (int)ceil(log((double)L));
        if (n > L) n = L;

        // QKV projections
        run_gemm(xb, wq + (size_t)l * 262144, bq + l * 512, qb, M, 512, 512, 0, 0, 0, 0);
        run_gemm(xb, wk + (size_t)l * 262144, bk + l * 512, kb, M, 512, 512, 0, 0, 0, 0);
        run_gemm(xb, wv + (size_t)l * 262144, bv + l * 512, vb, M, 512, 512, 0, 0, 0, 0);

        // sampling indices (threefry) + sparsity measure + top-k
        int tot = L * n;
        k_bits<<<(tot + 255) / 256, 256>>>(k1a[l], k1b[l], k2a[l], k2b[l], tot);
        k_randint<<<(tot + 255) / 256, 256>>>(tot, (unsigned)L);
        k_measure<<<(BB * NH * L * 32 + 255) / 256, 256>>>(qb, kb, mb, L, n);
        k_topk<<<BB * NH, 256>>>(mb, tpb, L, n);

        // context = mean(v) everywhere, then real attention on selected queries
        k_vmean<<<BB * NH, 256>>>(vb, vmb, L);
        k_fill<<<(BB * L * DM + 255) / 256, 256>>>(vmb, cxb, L);
        k_attn<<<BB * NH * n, 256>>>(qb, kb, vb, tpb, cxb, L, n);

        // out projection + residual LN1
        run_gemm(cxb, wo + (size_t)l * 262144, bo + l * 512, qb, M, 512, 512, 0, 0, 0, 0);
        k_ln<<<M, 128>>>(xb, qb, ln1w + l * 512, ln1b + l * 512, M);

        // FFN + residual LN2
        run_gemm(xb, ff1w + (size_t)l * 1048576, ff1b + l * 2048, fb, M, 2048, 512, 1, 0, 0, 0);
        run_gemm(fb, ff2w + (size_t)l * 1048576, ff2b + l * 512, qb, M, 512, 2048, 0, 0, 0, 0);
        k_ln<<<M, 128>>>(xb, qb, ln2w + l * 512, ln2b + l * 512, M);

        // distilling conv (layers 0,1) — 3 accumulating circular-shift GEMMs
        if (l < 2) {
            k_convw<<<(3 * DM * DM + 255) / 256, 256>>>(cvw + (size_t)l * 786432);
            for (int t = 0; t < 3; t++)
                run_gemm(xb, cwb + (size_t)t * 262144,
                         (t == 0) ? (cvb + l * 512) : (const float*)0,
                         fb, M, 512, 512, 0, t > 0, L, t - 1);
            int L2 = (L - 1) / 2 + 1;
            k_pool<<<(BB * L2 * DM + 255) / 256, 256>>>(fb, xb, bnw + l * 512, bnb + l * 512, L, L2);
            L = L2;
        }
    }

    // final norm + gelu + projection
    k_ln<<<BB * L, 128>>>(xb, (const float*)0, nw, nb, BB * L);
    k_proj<<<BB * 10, 256>>>(xb, pw, pb, out);
}

// round 13
// speedup vs baseline: 1.0180x; 1.0180x over previous
#include <cuda_runtime.h>
#include <cuda_bf16.h>
#include <math.h>

#define BB   8
#define DM   512
#define NH   8
#define DH   64
#define DFF  2048
#define LMAX 1021
#define NMAX 35

// ---------------- scratch (static device globals; no allocation) -------------
__device__ float g_x  [BB*LMAX*DM];
__device__ float g_q  [BB*LMAX*DM];
__device__ float g_k  [BB*LMAX*DM];
__device__ float g_v  [BB*LMAX*DM];
__device__ float g_ctx[BB*LMAX*DM];
__device__ float g_ffh[BB*LMAX*DFF];
__device__ float g_m  [BB*NH*LMAX];
__device__ float g_vmean[BB*NH*DH];
__device__ int   g_top[BB*NH*NMAX];
__device__ int   g_idx[LMAX*NMAX];
__device__ unsigned g_hi[LMAX*NMAX];
__device__ unsigned g_lo[LMAX*NMAX];
__device__ float g_cw [3*DM*DM];

// ---------------- threefry2x32 (20 rounds), host+device ----------------------
__host__ __device__ static inline unsigned rotl32(unsigned v, int d) {
    return (v << d) | (v >> (32 - d));
}
__host__ __device__ static inline void tf2x32(unsigned k0, unsigned k1,
                                              unsigned x0, unsigned x1,
                                              unsigned& o0, unsigned& o1) {
    unsigned ks2 = k0 ^ k1 ^ 0x1BD11BDAu;
    x0 += k0; x1 += k1;
#define TFR(r) { x0 += x1; x1 = rotl32(x1, r); x1 ^= x0; }
    TFR(13) TFR(15) TFR(26) TFR(6)   x0 += k1;  x1 += ks2 + 1u;
    TFR(17) TFR(29) TFR(16) TFR(24)  x0 += ks2; x1 += k0  + 2u;
    TFR(13) TFR(15) TFR(26) TFR(6)   x0 += k0;  x1 += k1  + 3u;
    TFR(17) TFR(29) TFR(16) TFR(24)  x0 += k1;  x1 += ks2 + 4u;
    TFR(13) TFR(15) TFR(26) TFR(6)   x0 += ks2; x1 += k0  + 5u;
#undef TFR
    o0 = x0; o1 = x1;
}

// ---------------- random bits + randint --------------------------------------
__global__ void k_bits(unsigned k1a, unsigned k1b, unsigned k2a, unsigned k2b, int total) {
    int e = blockIdx.x * 256 + threadIdx.x;
    if (e >= total) return;
    unsigned o0, o1;
    tf2x32(k1a, k1b, 0u, (unsigned)e, o0, o1);
    g_hi[e] = o0 ^ o1;
    tf2x32(k2a, k2b, 0u, (unsigned)e, o0, o1);
    g_lo[e] = o0 ^ o1;
}

__global__ void k_randint(int total, unsigned span) {
    int e = blockIdx.x * 256 + threadIdx.x;
    if (e >= total) return;
    unsigned mult = 65536u % span;
    mult = (mult * mult) % span;
    unsigned off = (g_hi[e] % span) * mult + (g_lo[e] % span);
    g_idx[e] = (int)(off % span);
}

// ---------------- token embedding + positional encoding ----------------------
__global__ void k_embed(const float* __restrict__ xe, const float* __restrict__ tw,
                        float* __restrict__ x, int L) {
    int i = blockIdx.x * 256 + threadIdx.x;
    if (i >= BB * L * DM) return;
    int dm  = i % DM;
    int rem = i / DM;
    int l   = rem % L;
    int b   = rem / L;
    int lm1 = (l == 0) ? L - 1 : l - 1;
    int lp1 = (l == L - 1) ? 0 : l + 1;
    const float* x0 = xe + (size_t)(b * L + lm1) * 12;
    const float* x1 = xe + (size_t)(b * L + l)   * 12;
    const float* x2 = xe + (size_t)(b * L + lp1) * 12;
    const float* wp = tw + (size_t)dm * 36;
    float acc = 0.f;
#pragma unroll
    for (int c = 0; c < 12; c++)
        acc += x0[c] * wp[c * 3] + x1[c] * wp[c * 3 + 1] + x2[c] * wp[c * 3 + 2];
    float freq = expf((float)((dm >> 1) * 2) * (-1.7988946039015980e-2f)); // -ln(1e4)/512
    float a = (float)l * freq;
    acc += (dm & 1) ? cosf(a) : sinf(a);
    x[i] = acc;
}

// ---------------- 3xBF16 tensor-core GEMM: C = act(A*W^T [+C] [+bias]) -------
// A: M x K (optional per-batch circular row shift), W: N x K row-major.
// Operands split hi/lo in bf16 at smem-store time; 3 MMAs (m16n8k16) per pair:
// hi*hi + hi*lo + lo*hi, fp32 accumulate. Effective precision ~2^-16 per input.

__device__ __forceinline__ void mma_bf16(float* c, const unsigned* a, const unsigned* b) {
    asm volatile(
        "mma.sync.aligned.m16n8k16.row.col.f32.bf16.bf16.f32 "
        "{%0,%1,%2,%3}, {%4,%5,%6,%7}, {%8,%9}, {%0,%1,%2,%3};"
        : "+f"(c[0]), "+f"(c[1]), "+f"(c[2]), "+f"(c[3])
        : "r"(a[0]), "r"(a[1]), "r"(a[2]), "r"(a[3]), "r"(b[0]), "r"(b[1]));
}

// split a pair of floats into packed bf16x2 hi and lo words
__device__ __forceinline__ void split2(float x0, float x1, unsigned& hi, unsigned& lo) {
    __nv_bfloat162 h = __floats2bfloat162_rn(x0, x1);
    float h0 = __bfloat162float(h.x), h1 = __bfloat162float(h.y);
    __nv_bfloat162 l = __floats2bfloat162_rn(x0 - h0, x1 - h1);
    hi = *(unsigned*)&h;
    lo = *(unsigned*)&l;
}

#define KW 20  // 16 k-words (32 bf16) + pad 4 -> conflict-free fragment loads

__global__ void __launch_bounds__(256, 2)
k_gemm(const float* __restrict__ A, const float* __restrict__ W,
       const float* __restrict__ bias, float* __restrict__ C,
       int M, int N, int K, int act, int accum, int circL, int shift) {
    __shared__ unsigned AsH[128][KW], AsL[128][KW];
    __shared__ unsigned BsH[128][KW], BsL[128][KW];

    int bm = blockIdx.y * 128, bn = blockIdx.x * 128;
    int tid  = threadIdx.x;
    int warp = tid >> 5, lane = tid & 31;
    int wm = warp >> 2;          // 0..1 -> m offset wm*64
    int wn = warp & 3;           // 0..3 -> n offset wn*32
    int g  = lane >> 2;          // 0..7
    int cq = lane & 3;           // 0..3

    // load assignment: 2 threads per row, 16 floats (8 words) each
    int lrow = tid >> 1;
    int kqf  = (tid & 1) * 16;   // float offset within 32-wide k tile
    int kqw  = (tid & 1) * 8;    // word offset

    // A row mapping (circular shift for conv variant)
    int grow = bm + lrow;
    long arow = -1;
    if (grow < M) {
        if (circL > 0) {
            int b_ = grow / circL;
            int l_ = grow - b_ * circL + shift;
            if (l_ < 0) l_ += circL;
            if (l_ >= circL) l_ -= circL;
            arow = (long)b_ * circL + l_;
        } else arow = grow;
    }
    int wrow = bn + lrow; // N multiple of 128

    float acc[4][4][4];
#pragma unroll
    for (int i = 0; i < 4; i++)
#pragma unroll
        for (int j = 0; j < 4; j++)
#pragma unroll
            for (int e = 0; e < 4; e++) acc[i][j][e] = 0.f;

    for (int kt = 0; kt < K; kt += 32) {
#pragma unroll
        for (int i = 0; i < 4; i++) {
            float4 av = make_float4(0.f, 0.f, 0.f, 0.f);
            if (arow >= 0) av = *(const float4*)(A + (size_t)arow * K + kt + kqf + i * 4);
            unsigned h0, l0, h1, l1;
            split2(av.x, av.y, h0, l0);
            split2(av.z, av.w, h1, l1);
            AsH[lrow][kqw + 2 * i]     = h0;
            AsH[lrow][kqw + 2 * i + 1] = h1;
            AsL[lrow][kqw + 2 * i]     = l0;
            AsL[lrow][kqw + 2 * i + 1] = l1;

            float4 wv = *(const float4*)(W + (size_t)wrow * K + kt + kqf + i * 4);
            split2(wv.x, wv.y, h0, l0);
            split2(wv.z, wv.w, h1, l1);
            BsH[lrow][kqw + 2 * i]     = h0;
            BsH[lrow][kqw + 2 * i + 1] = h1;
            BsL[lrow][kqw + 2 * i]     = l0;
            BsL[lrow][kqw + 2 * i + 1] = l1;
        }
        __syncthreads();

#pragma unroll
        for (int ks = 0; ks < 2; ks++) {
            int kb = ks * 8;
            unsigned bh[4][2], bl[4][2];
#pragma unroll
            for (int j = 0; j < 4; j++) {
                int n0 = wn * 32 + j * 8 + g;
                bh[j][0] = BsH[n0][kb + cq];
                bh[j][1] = BsH[n0][kb + cq + 4];
                bl[j][0] = BsL[n0][kb + cq];
                bl[j][1] = BsL[n0][kb + cq + 4];
            }
#pragma unroll
            for (int i = 0; i < 4; i++) {
                int m0 = wm * 64 + i * 16;
                unsigned ah[4], al[4];
                ah[0] = AsH[m0 + g    ][kb + cq];
                ah[1] = AsH[m0 + g + 8][kb + cq];
                ah[2] = AsH[m0 + g    ][kb + cq + 4];
                ah[3] = AsH[m0 + g + 8][kb + cq + 4];
                al[0] = AsL[m0 + g    ][kb + cq];
                al[1] = AsL[m0 + g + 8][kb + cq];
                al[2] = AsL[m0 + g    ][kb + cq + 4];
                al[3] = AsL[m0 + g + 8][kb + cq + 4];
#pragma unroll
                for (int j = 0; j < 4; j++) {
                    mma_bf16(acc[i][j], ah, bl[j]);   // hi * lo
                    mma_bf16(acc[i][j], al, bh[j]);   // lo * hi
                    mma_bf16(acc[i][j], ah, bh[j]);   // hi * hi
                }
            }
        }
        __syncthreads();
    }

    // epilogue
#pragma unroll
    for (int i = 0; i < 4; i++) {
        int r0 = bm + wm * 64 + i * 16 + g;
        int r1 = r0 + 8;
#pragma unroll
        for (int j = 0; j < 4; j++) {
            int col = bn + wn * 32 + j * 8 + 2 * cq;
#pragma unroll
            for (int hrow = 0; hrow < 2; hrow++) {
                int r = hrow ? r1 : r0;
                if (r >= M) continue;
                float v0 = acc[i][j][hrow * 2 + 0];
                float v1 = acc[i][j][hrow * 2 + 1];
                size_t base = (size_t)r * N + col;
                if (accum) { v0 += C[base]; v1 += C[base + 1]; }
                if (bias)  { v0 += bias[col]; v1 += bias[col + 1]; }
                if (act == 1) {
                    v0 = 0.5f * v0 * (1.f + erff(v0 * 0.70710678118654752f));
                    v1 = 0.5f * v1 * (1.f + erff(v1 * 0.70710678118654752f));
                }
                C[base] = v0; C[base + 1] = v1;
            }
        }
    }
}

// ---------------- residual + layernorm (in place on x) -----------------------
__global__ void k_ln(float* __restrict__ x, const float* __restrict__ r,
                     const float* __restrict__ w, const float* __restrict__ b, int Mrows) {
    int row = blockIdx.x;
    if (row >= Mrows) return;
    int tid = threadIdx.x; // 128 threads, 4 elems each
    float4 v = *(float4*)(x + (size_t)row * DM + tid * 4);
    if (r) {
        float4 rv = *(const float4*)(r + (size_t)row * DM + tid * 4);
        v.x += rv.x; v.y += rv.y; v.z += rv.z; v.w += rv.w;
    }
    __shared__ float a1[128], a2[128];
    a1[tid] = v.x + v.y + v.z + v.w;
    a2[tid] = v.x * v.x + v.y * v.y + v.z * v.z + v.w * v.w;
    __syncthreads();
    for (int s = 64; s > 0; s >>= 1) {
        if (tid < s) { a1[tid] += a1[tid + s]; a2[tid] += a2[tid + s]; }
        __syncthreads();
    }
    float mean = a1[0] * (1.f / 512.f);
    float var  = a2[0] * (1.f / 512.f) - mean * mean;
    float rs   = rsqrtf(var + 1e-5f);
    int c = tid * 4;
    float4 o;
    o.x = (v.x - mean) * rs * w[c + 0] + b[c + 0];
    o.y = (v.y - mean) * rs * w[c + 1] + b[c + 1];
    o.z = (v.z - mean) * rs * w[c + 2] + b[c + 2];
    o.w = (v.w - mean) * rs * w[c + 3] + b[c + 3];
    *(float4*)(x + (size_t)row * DM + tid * 4) = o;
}

// ---------------- sparsity measure m[b,h,l] -----------------------------------
__global__ void k_measure(const float* __restrict__ q, const float* __restrict__ k,
                          float* __restrict__ m, int L, int n) {
    int w = (blockIdx.x * blockDim.x + threadIdx.x) >> 5;
    int lane = threadIdx.x & 31;
    if (w >= BB * NH * L) return;
    int l  = w % L;
    int bh = w / L;
    int h  = bh % NH;
    int b  = bh / NH;
    const float* qp = q + ((size_t)(b * L + l) * DM + h * DH);
    float q0 = qp[lane], q1 = qp[lane + 32];
    float mx = -INFINITY, sm = 0.f;
    const int* idx = g_idx + l * n;
    for (int s = 0; s < n; s++) {
        int j = idx[s];
        const float* kp = k + ((size_t)(b * L + j) * DM + h * DH);
        float d = q0 * kp[lane] + q1 * kp[lane + 32];
#pragma unroll
        for (int o = 16; o > 0; o >>= 1) d += __shfl_xor_sync(0xffffffffu, d, o);
        mx = fmaxf(mx, d);
        sm += d;
    }
    if (lane == 0) m[(size_t)bh * L + l] = mx - sm / (float)L;
}

// ---------------- per-(b,h) iterative top-k -----------------------------------
__global__ void k_topk(const float* __restrict__ m, int* __restrict__ top, int L, int n) {
    __shared__ float sm[1024];
    __shared__ float rv[256];
    __shared__ int   ri[256];
    int bh = blockIdx.x;
    int tid = threadIdx.x;
    for (int i = tid; i < 1024; i += 256) sm[i] = (i < L) ? m[(size_t)bh * L + i] : -INFINITY;
    __syncthreads();
    for (int it = 0; it < n; it++) {
        float bv = -INFINITY; int bi = 0x7fffffff;
        for (int i = tid; i < L; i += 256) {
            float v = sm[i];
            if (v > bv) { bv = v; bi = i; }
        }
        rv[tid] = bv; ri[tid] = bi;
        __syncthreads();
        for (int s = 128; s > 0; s >>= 1) {
            if (tid < s) {
                float v2 = rv[tid + s]; int i2 = ri[tid + s];
                if (v2 > rv[tid] || (v2 == rv[tid] && i2 < ri[tid])) { rv[tid] = v2; ri[tid] = i2; }
            }
            __syncthreads();
        }
        if (tid == 0) { top[bh * n + it] = ri[0]; sm[ri[0]] = -INFINITY; }
        __syncthreads();
    }
}

// ---------------- mean(v) and context fill ------------------------------------
__global__ void k_vmean(const float* __restrict__ v, float* __restrict__ vm, int L) {
    __shared__ float red[256];
    int bh = blockIdx.x;
    int tid = threadIdx.x;      // 256 threads: d = tid%64, part = tid/64
    int d = tid & 63, part = tid >> 6;
    int h = bh % NH, b = bh / NH;
    float acc = 0.f;
    for (int l = part; l < L; l += 4)
        acc += v[(size_t)(b * L + l) * DM + h * DH + d];
    red[tid] = acc;
    __syncthreads();
    if (tid < 128) red[tid] += red[tid + 128];
    __syncthreads();
    if (tid < 64) vm[bh * DH + d] = (red[tid] + red[tid + 64]) / (float)L;
}
__global__ void k_fill(const float* __restrict__ vm, float* __restrict__ ctx, int L) {
    int i = blockIdx.x * 256 + threadIdx.x;
    if (i >= BB * L * DM) return;
    int c  = i % DM;
    int bl = i / DM;
    int b  = bl / L;
    ctx[i] = vm[(b * NH + (c >> 6)) * DH + (c & 63)];
}

// ---------------- full attention for the n selected queries -------------------
__global__ void k_attn(const float* __restrict__ q, const float* __restrict__ k,
                       const float* __restrict__ v, const int* __restrict__ top,
                       float* __restrict__ ctx, int L, int n) {
    __shared__ float sc[1024];
    __shared__ float qs[64];
    __shared__ float red[256];
    int u  = blockIdx.x % n;
    int bh = blockIdx.x / n;
    int h = bh % NH, b = bh / NH;
    int tid = threadIdx.x;
    int lq = top[bh * n + u];
    if (tid < 64) qs[tid] = q[(size_t)(b * L + lq) * DM + h * DH + tid];
    __syncthreads();
    int warp = tid >> 5, lane = tid & 31;
    for (int lk = warp; lk < L; lk += 8) {
        const float* kp = k + ((size_t)(b * L + lk) * DM + h * DH);
        float d = qs[lane] * kp[lane] + qs[lane + 32] * kp[lane + 32];
#pragma unroll
        for (int o = 16; o > 0; o >>= 1) d += __shfl_xor_sync(0xffffffffu, d, o);
        if (lane == 0) sc[lk] = d * 0.125f;
    }
    __syncthreads();
    float mx = -INFINITY;
    for (int i = tid; i < L; i += 256) mx = fmaxf(mx, sc[i]);
    red[tid] = mx;
    __syncthreads();
    for (int s = 128; s > 0; s >>= 1) {
        if (tid < s) red[tid] = fmaxf(red[tid], red[tid + s]);
        __syncthreads();
    }
    mx = red[0];
    __syncthreads();
    float sum = 0.f;
    for (int i = tid; i < L; i += 256) {
        float e = expf(sc[i] - mx);
        sc[i] = e;
        sum += e;
    }
    red[tid] = sum;
    __syncthreads();
    for (int s = 128; s > 0; s >>= 1) {
        if (tid < s) red[tid] += red[tid + s];
        __syncthreads();
    }
    float inv = 1.f / red[0];
    __syncthreads();
    int d = tid & 63, part = tid >> 6;
    float acc = 0.f;
    for (int lk = part; lk < L; lk += 4)
        acc += sc[lk] * v[(size_t)(b * L + lk) * DM + h * DH + d];
    red[tid] = acc;
    __syncthreads();
    if (tid < 64) {
        float s2 = red[tid] + red[tid + 64] + red[tid + 128] + red[tid + 192];
        ctx[(size_t)(b * L + lq) * DM + h * DH + tid] = s2 * inv;
    }
}

// ---------------- conv weight repack (tap-major) -------------------------------
__global__ void k_convw(const float* __restrict__ cw) {
    int i = blockIdx.x * 256 + threadIdx.x;
    if (i >= 3 * DM * DM) return;
    int t = i / (DM * DM);
    int rem = i % (DM * DM);
    g_cw[i] = cw[(size_t)rem * 3 + t];
}

// ---------------- BN + ELU + maxpool(3, stride 2, pad 1) -----------------------
__global__ void k_pool(const float* __restrict__ hin, float* __restrict__ xout,
                       const float* __restrict__ bnw, const float* __restrict__ bnb,
                       int L, int L2) {
    int i = blockIdx.x * 256 + threadIdx.x;
    if (i >= BB * L2 * DM) return;
    int c = i % DM;
    int rem = i / DM;
    int l2 = rem % L2;
    int b  = rem / L2;
    float s  = bnw[c] * 0.99999500003749977f; // 1/sqrt(1+1e-5)
    float sh = bnb[c];
    float best = -INFINITY;
#pragma unroll
    for (int dj = -1; dj <= 1; dj++) {
        int j = 2 * l2 + dj;
        if (j < 0 || j >= L) continue;
        float vv = hin[(size_t)(b * L + j) * DM + c] * s + sh;
        vv = (vv > 0.f) ? vv : expm1f(vv);
        best = fmaxf(best, vv);
    }
    xout[(size_t)(b * L2 + l2) * DM + c] = best;
}

// ---------------- final: gelu(x) flattened @ proj^T + bias ---------------------
__global__ void k_proj(const float* __restrict__ x, const float* __restrict__ pw,
                       const float* __restrict__ pb, float* __restrict__ out) {
    int cls = blockIdx.x % 10, b = blockIdx.x / 10;
    int tid = threadIdx.x;
    const float* xp = x  + (size_t)b   * 131072;
    const float* wp = pw + (size_t)cls * 131072;
    float acc = 0.f;
    for (int i = tid; i < 131072; i += 256) {
        float xv = xp[i];
        float g = 0.5f * xv * (1.f + erff(xv * 0.70710678118654752f));
        acc += g * wp[i];
    }
    __shared__ float red[256];
    red[tid] = acc;
    __syncthreads();
    for (int s = 128; s > 0; s >>= 1) {
        if (tid < s) red[tid] += red[tid + s];
        __syncthreads();
    }
    if (tid == 0) out[b * 10 + cls] = red[0] + pb[cls];
}

// ---------------- host orchestration -------------------------------------------
static void run_gemm(const float* A, const float* W, const float* bias, float* C,
                     int M, int N, int K, int act, int accum, int circL, int shift) {
    dim3 grid(N / 128, (M + 127) / 128);
    k_gemm<<<grid, 256>>>(A, W, bias, C, M, N, K, act, accum, circL, shift);
}

extern "C" void kernel_launch(void* const* d_in, const int* in_sizes, int n_in,
                              void* d_out, int out_size) {
    const float* x_enc = (const float*)d_in[0];
    const float* tok_w = (const float*)d_in[1];
    const float* wq  = (const float*)d_in[2];
    const float* bq  = (const float*)d_in[3];
    const float* wk  = (const float*)d_in[4];
    const float* bk  = (const float*)d_in[5];
    const float* wv  = (const float*)d_in[6];
    const float* bv  = (const float*)d_in[7];
    const float* wo  = (const float*)d_in[8];
    const float* bo  = (const float*)d_in[9];
    const float* ln1w = (const float*)d_in[10];
    const float* ln1b = (const float*)d_in[11];
    const float* ln2w = (const float*)d_in[12];
    const float* ln2b = (const float*)d_in[13];
    const float* ff1w = (const float*)d_in[14];
    const float* ff1b = (const float*)d_in[15];
    const float* ff2w = (const float*)d_in[16];
    const float* ff2b = (const float*)d_in[17];
    const float* cvw = (const float*)d_in[18];
    const float* cvb = (const float*)d_in[19];
    const float* bnw = (const float*)d_in[20];
    const float* bnb = (const float*)d_in[21];
    const float* nw  = (const float*)d_in[22];
    const float* nb  = (const float*)d_in[23];
    const float* pw  = (const float*)d_in[24];
    const float* pb  = (const float*)d_in[25];
    float* out = (float*)d_out;

    float *xb, *qb, *kb, *vb, *cxb, *fb, *mb, *vmb, *cwb;
    int *tpb;
    cudaGetSymbolAddress((void**)&xb,  g_x);
    cudaGetSymbolAddress((void**)&qb,  g_q);
    cudaGetSymbolAddress((void**)&kb,  g_k);
    cudaGetSymbolAddress((void**)&vb,  g_v);
    cudaGetSymbolAddress((void**)&cxb, g_ctx);
    cudaGetSymbolAddress((void**)&fb,  g_ffh);
    cudaGetSymbolAddress((void**)&mb,  g_m);
    cudaGetSymbolAddress((void**)&vmb, g_vmean);
    cudaGetSymbolAddress((void**)&tpb, g_top);
    cudaGetSymbolAddress((void**)&cwb, g_cw);

    // ---- per-layer threefry keys (jax.random.split(key(42), 3), partitionable) ----
    unsigned k1a[3], k1b[3], k2a[3], k2b[3];
    for (int l = 0; l < 3; l++) {
        unsigned ka, kb2;
        tf2x32(0u, 42u, 0u, (unsigned)l, ka, kb2);       // layer key
        tf2x32(ka, kb2, 0u, 0u, k1a[l], k1b[l]);         // randint higher key
        tf2x32(ka, kb2, 0u, 1u, k2a[l], k2b[l]);         // randint lower key
    }

    int L = LMAX;
    k_embed<<<(BB * L * DM + 255) / 256, 256>>>(x_enc, tok_w, xb, L);

    for (int l = 0; l < 3; l++) {
        int M = BB * L;
        int n = 5 * (int)ceil(log((double)L));
        if (n > L) n = L;

        // QKV projections
        run_gemm(xb, wq + (size_t)l * 262144, bq + l * 512, qb, M, 512, 512, 0, 0, 0, 0);
        run_gemm(xb, wk + (size_t)l * 262144, bk + l * 512, kb, M, 512, 512, 0, 0, 0, 0);
        run_gemm(xb, wv + (size_t)l * 262144, bv + l * 512, vb, M, 512, 512, 0, 0, 0, 0);

        // sampling indices (threefry) + sparsity measure + top-k
        int tot = L * n;
        k_bits<<<(tot + 255) / 256, 256>>>(k1a[l], k1b[l], k2a[l], k2b[l], tot);
        k_randint<<<(tot + 255) / 256, 256>>>(tot, (unsigned)L);
        k_measure<<<(BB * NH * L * 32 + 255) / 256, 256>>>(qb, kb, mb, L, n);
        k_topk<<<BB * NH, 256>>>(mb, tpb, L, n);

        // context = mean(v) everywhere, then real attention on selected queries
        k_vmean<<<BB * NH, 256>>>(vb, vmb, L);
        k_fill<<<(BB * L * DM + 255) / 256, 256>>>(vmb, cxb, L);
        k_attn<<<BB * NH * n, 256>>>(qb, kb, vb, tpb, cxb, L, n);

        // out projection + residual LN1
        run_gemm(cxb, wo + (size_t)l * 262144, bo + l * 512, qb, M, 512, 512, 0, 0, 0, 0);
        k_ln<<<M, 128>>>(xb, qb, ln1w + l * 512, ln1b + l * 512, M);

        // FFN + residual LN2
        run_gemm(xb, ff1w + (size_t)l * 1048576, ff1b + l * 2048, fb, M, 2048, 512, 1, 0, 0, 0);
        run_gemm(fb, ff2w + (size_t)l * 1048576, ff2b + l * 512, qb, M, 512, 2048, 0, 0, 0, 0);
        k_ln<<<M, 128>>>(xb, qb, ln2w + l * 512, ln2b + l * 512, M);

        // distilling conv (layers 0,1) — 3 accumulating circular-shift GEMMs
        if (l < 2) {
            k_convw<<<(3 * DM * DM + 255) / 256, 256>>>(cvw + (size_t)l * 786432);
            for (int t = 0; t < 3; t++)
                run_gemm(xb, cwb + (size_t)t * 262144,
                         (t == 0) ? (cvb + l * 512) : (const float*)0,
                         fb, M, 512, 512, 0, t > 0, L, t - 1);
            int L2 = (L - 1) / 2 + 1;
            k_pool<<<(BB * L2 * DM + 255) / 256, 256>>>(fb, xb, bnw + l * 512, bnb + l * 512, L, L2);
            L = L2;
        }
    }

    // final norm + gelu + projection
    k_ln<<<BB * L, 128>>>(xb, (const float*)0, nw, nb, BB * L);
    k_proj<<<BB * 10, 256>>>(xb, pw, pb, out);
}